// round 2
// baseline (speedup 1.0000x reference)
#include <cuda_runtime.h>
#include <math.h>

#define NN  100000
#define EE  1600000
#define HIDD 128

// Scratch (allowed: __device__ global arrays)
__device__ float g_agg[(size_t)NN * HIDD];
__device__ float g_h0 [(size_t)NN * HIDD];
__device__ float g_h1 [(size_t)NN * HIDD];

// ---------------------------------------------------------------------------
// zero the aggregation buffer
// ---------------------------------------------------------------------------
__global__ void zero_kernel(float4* __restrict__ p, int n4) {
    int i = blockIdx.x * blockDim.x + threadIdx.x;
    if (i < n4) p[i] = make_float4(0.f, 0.f, 0.f, 0.f);
}

// ---------------------------------------------------------------------------
// scatter-add: agg[dst] += h[src], one warp per edge, float4 atomics (sm_90+)
// edge_index is INT32 (jax x64 disabled downcasts int64 -> int32)
// ---------------------------------------------------------------------------
__global__ void scatter_kernel(const float* __restrict__ h,
                               const int* __restrict__ ei,
                               float* __restrict__ agg) {
    long long gid = (long long)blockIdx.x * blockDim.x + threadIdx.x;
    long long e   = gid >> 5;
    int lane      = threadIdx.x & 31;
    if (e >= EE) return;
    long long s = (long long)ei[e];
    long long d = (long long)ei[(long long)EE + e];
    float4 v = *reinterpret_cast<const float4*>(h + s * HIDD + lane * 4);
    atomicAdd(reinterpret_cast<float4*>(agg + d * HIDD + lane * 4), v);
}

// ---------------------------------------------------------------------------
// fused GIN MLP: hout = elu( relu( (hin+agg) @ Wa + ba ) @ Wb + bb )
// Block: 64 node rows, 256 threads. Both 128x128 weights in smem (160KB dyn).
// Thread micro-tile: 8 rows x 4 cols. ct = tid&31 (col/4), rt = tid>>5 (row/8).
// ---------------------------------------------------------------------------
__global__ void __launch_bounds__(256, 1)
mlp_kernel(const float* __restrict__ hin, const float* __restrict__ agg,
           const float* __restrict__ wa,  const float* __restrict__ ba,
           const float* __restrict__ wb,  const float* __restrict__ bb,
           float* __restrict__ hout) {
    extern __shared__ float smem[];
    float* sWA = smem;               // 128*128 = 16384 floats
    float* sWB = smem + 16384;       // 16384 floats
    float* sX  = smem + 32768;       // 64*128 = 8192 floats

    const int tid = threadIdx.x;
    const int m0  = blockIdx.x * 64;

    // load weights into smem (coalesced float4)
    const float4* wa4 = reinterpret_cast<const float4*>(wa);
    const float4* wb4 = reinterpret_cast<const float4*>(wb);
    float4* sWA4 = reinterpret_cast<float4*>(sWA);
    float4* sWB4 = reinterpret_cast<float4*>(sWB);
#pragma unroll
    for (int it = 0; it < 16; ++it) {
        sWA4[tid + 256 * it] = wa4[tid + 256 * it];
        sWB4[tid + 256 * it] = wb4[tid + 256 * it];
    }

    // load node tile: sX[row][k] = hin + agg (zeros for out-of-range rows)
    float4* sX4 = reinterpret_cast<float4*>(sX);
#pragma unroll
    for (int it = 0; it < 8; ++it) {
        int p   = tid + 256 * it;      // float4 index in 64x128 tile
        int row = p >> 5;              // 32 float4 per row
        float4 v = make_float4(0.f, 0.f, 0.f, 0.f);
        if (m0 + row < NN) {
            long long g = (long long)(m0 + row) * HIDD + (p & 31) * 4;
            float4 a = *reinterpret_cast<const float4*>(hin + g);
            float4 b = *reinterpret_cast<const float4*>(agg + g);
            v = make_float4(a.x + b.x, a.y + b.y, a.z + b.z, a.w + b.w);
        }
        sX4[p] = v;
    }
    __syncthreads();

    const int ct = tid & 31;
    const int rt = tid >> 5;

    // ---- GEMM 1: (x+agg) @ Wa + ba, then ReLU ----
    float acc[8][4];
    {
        float4 bA = reinterpret_cast<const float4*>(ba)[ct];
#pragma unroll
        for (int i = 0; i < 8; ++i) {
            acc[i][0] = bA.x; acc[i][1] = bA.y; acc[i][2] = bA.z; acc[i][3] = bA.w;
        }
    }
#pragma unroll 4
    for (int k = 0; k < HIDD; ++k) {
        float4 bcol = reinterpret_cast<const float4*>(sWA + k * HIDD)[ct];
#pragma unroll
        for (int i = 0; i < 8; ++i) {
            float a = sX[(rt * 8 + i) * HIDD + k];   // warp broadcast
            acc[i][0] += a * bcol.x;
            acc[i][1] += a * bcol.y;
            acc[i][2] += a * bcol.z;
            acc[i][3] += a * bcol.w;
        }
    }
    __syncthreads();
    // ReLU, write intermediate back to sX
#pragma unroll
    for (int i = 0; i < 8; ++i) {
        float4 v = make_float4(fmaxf(acc[i][0], 0.f), fmaxf(acc[i][1], 0.f),
                               fmaxf(acc[i][2], 0.f), fmaxf(acc[i][3], 0.f));
        reinterpret_cast<float4*>(sX + (rt * 8 + i) * HIDD)[ct] = v;
    }
    __syncthreads();

    // ---- GEMM 2: h @ Wb + bb, then ELU ----
    {
        float4 bB = reinterpret_cast<const float4*>(bb)[ct];
#pragma unroll
        for (int i = 0; i < 8; ++i) {
            acc[i][0] = bB.x; acc[i][1] = bB.y; acc[i][2] = bB.z; acc[i][3] = bB.w;
        }
    }
#pragma unroll 4
    for (int k = 0; k < HIDD; ++k) {
        float4 bcol = reinterpret_cast<const float4*>(sWB + k * HIDD)[ct];
#pragma unroll
        for (int i = 0; i < 8; ++i) {
            float a = sX[(rt * 8 + i) * HIDD + k];
            acc[i][0] += a * bcol.x;
            acc[i][1] += a * bcol.y;
            acc[i][2] += a * bcol.z;
            acc[i][3] += a * bcol.w;
        }
    }

    // ELU + global store
#pragma unroll
    for (int i = 0; i < 8; ++i) {
        int row = m0 + rt * 8 + i;
        if (row < NN) {
            float4 v;
            v.x = acc[i][0] > 0.f ? acc[i][0] : expf(acc[i][0]) - 1.f;
            v.y = acc[i][1] > 0.f ? acc[i][1] : expf(acc[i][1]) - 1.f;
            v.z = acc[i][2] > 0.f ? acc[i][2] : expf(acc[i][2]) - 1.f;
            v.w = acc[i][3] > 0.f ? acc[i][3] : expf(acc[i][3]) - 1.f;
            reinterpret_cast<float4*>(hout + (long long)row * HIDD)[ct] = v;
        }
    }
}

// ---------------------------------------------------------------------------
// final: out[i] = sigmoid( dot(h[i], lin_w) + lin_b ), one warp per node
// ---------------------------------------------------------------------------
__global__ void final_kernel(const float* __restrict__ h,
                             const float* __restrict__ lw,
                             const float* __restrict__ lb,
                             float* __restrict__ out) {
    int warp = (blockIdx.x * blockDim.x + threadIdx.x) >> 5;
    int lane = threadIdx.x & 31;
    if (warp >= NN) return;
    const float* row = h + (long long)warp * HIDD;
    float s = 0.f;
#pragma unroll
    for (int i = 0; i < 4; ++i)
        s += row[lane + 32 * i] * lw[lane + 32 * i];
#pragma unroll
    for (int o = 16; o; o >>= 1)
        s += __shfl_xor_sync(0xFFFFFFFFu, s, o);
    if (lane == 0)
        out[warp] = 1.f / (1.f + expf(-(s + lb[0])));
}

// ---------------------------------------------------------------------------
extern "C" void kernel_launch(void* const* d_in, const int* in_sizes, int n_in,
                              void* d_out, int out_size) {
    const float* x   = (const float*)d_in[0];
    const int*   ei  = (const int*)d_in[1];   // int32! (jax default x64 disabled)
    const float* Wa[3] = { (const float*)d_in[2],  (const float*)d_in[6],  (const float*)d_in[10] };
    const float* Ba[3] = { (const float*)d_in[3],  (const float*)d_in[7],  (const float*)d_in[11] };
    const float* Wb[3] = { (const float*)d_in[4],  (const float*)d_in[8],  (const float*)d_in[12] };
    const float* Bb[3] = { (const float*)d_in[5],  (const float*)d_in[9],  (const float*)d_in[13] };
    const float* lin_w = (const float*)d_in[14];
    const float* lin_b = (const float*)d_in[15];
    float* out = (float*)d_out;

    float *agg, *h0, *h1;
    cudaGetSymbolAddress((void**)&agg, g_agg);
    cudaGetSymbolAddress((void**)&h0,  g_h0);
    cudaGetSymbolAddress((void**)&h1,  g_h1);

    cudaFuncSetAttribute(mlp_kernel,
                         cudaFuncAttributeMaxDynamicSharedMemorySize, 163840);

    const int n4      = NN * HIDD / 4;
    const int zblocks = (n4 + 255) / 256;
    const int sblocks = (int)(((long long)EE * 32 + 255) / 256);
    const int mblocks = (NN + 63) / 64;

    const float* hin = x;
    float* bufs[3] = { h0, h1, h0 };

    for (int l = 0; l < 3; ++l) {
        zero_kernel   <<<zblocks, 256>>>((float4*)agg, n4);
        scatter_kernel<<<sblocks, 256>>>(hin, ei, agg);
        mlp_kernel    <<<mblocks, 256, 163840>>>(hin, agg, Wa[l], Ba[l], Wb[l], Bb[l], bufs[l]);
        hin = bufs[l];
    }

    final_kernel<<<(NN * 32 + 255) / 256, 256>>>(hin, lin_w, lin_b, out);
}